// round 15
// baseline (speedup 1.0000x reference)
#include <cuda_runtime.h>
#include <cuda_fp16.h>
#include <cstdint>
#include <cstddef>

constexpr int B_ = 16, N_ = 2048, D_ = 64;
constexpr size_t ND = (size_t)N_ * D_;
constexpr size_t N2 = (size_t)N_ * N_;
// fragment-tiled P: tile (qt,kt) = 128q x 64k = 8192 elements
// idx = w*1024 + (mt*4+nt)*128 + lane*4 + e
constexpr int TILE = 8192;

// ---- scratch (__device__ globals; no allocations allowed) ----
__device__ __half g_P[(size_t)B_ * N2];       // fragment-tiled exp(scores), fp16 (134MB)
__device__ float g_rdenom[N2];                // fragment-tiled, fp32 (16MB)
__device__ __half g_Qf[(size_t)B_ * ND];      // fp16 single plane (scale folded)
__device__ __half g_Kf[(size_t)B_ * ND];      // fp16 single plane
// V in B-fragment layout (fp16 single plane):
// slot = ((b*32 + c)*16 + kh*8 + kg*4 + g16), entry [slot*32 + lane]
__device__ uint4 g_VFf[262144];               // 4MB

#define SW128(o) ((o) ^ (((o) >> 3) & 0x70))

__device__ __forceinline__ uint32_t smem_u32(const void* p) {
    uint32_t a;
    asm("{ .reg .u64 t; cvta.to.shared.u64 t, %1; cvt.u32.u64 %0, t; }" : "=r"(a) : "l"(p));
    return a;
}
__device__ __forceinline__ void ldmx4(uint32_t* r, uint32_t addr) {
    asm volatile("ldmatrix.sync.aligned.m8n8.x4.shared.b16 {%0,%1,%2,%3}, [%4];"
                 : "=r"(r[0]), "=r"(r[1]), "=r"(r[2]), "=r"(r[3]) : "r"(addr));
}
__device__ __forceinline__ void mma16816(float* d, const uint32_t* a, uint32_t b0, uint32_t b1) {
    asm volatile(
        "mma.sync.aligned.m16n8k16.row.col.f32.f16.f16.f32 "
        "{%0,%1,%2,%3}, {%4,%5,%6,%7}, {%8,%9}, {%0,%1,%2,%3};"
        : "+f"(d[0]), "+f"(d[1]), "+f"(d[2]), "+f"(d[3])
        : "r"(a[0]), "r"(a[1]), "r"(a[2]), "r"(a[3]), "r"(b0), "r"(b1));
}
__device__ __forceinline__ uint32_t pack2h(float a, float b) {
    __half2 v = __floats2half2_rn(a, b);
    return *(uint32_t*)&v;
}
__device__ __forceinline__ void cp16(uint32_t dst, const void* src) {
    asm volatile("cp.async.cg.shared.global [%0], [%1], 16;" :: "r"(dst), "l"(src));
}
__device__ __forceinline__ void cp8(uint32_t dst, const void* src) {
    asm volatile("cp.async.ca.shared.global [%0], [%1], 8;" :: "r"(dst), "l"(src));
}
__device__ __forceinline__ void cp_commit() {
    asm volatile("cp.async.commit_group;" ::: "memory");
}

// ===========================================================================
// k0_prep (merged): flat grid of 2560 blocks x 256 thr
//   [0,1024):    K -> single fp16 plane
//   [1024,1536): V -> B-fragment layout (fp16 single plane) via smem tile
//   [1536,2560): Q -> single fp16 plane (scale folded)
// ===========================================================================
__global__ __launch_bounds__(256) void k0_prep(const float* __restrict__ Q,
                                               const float* __restrict__ K,
                                               const float* __restrict__ V) {
    __shared__ float smv[64][65];
    const int bid = blockIdx.x;
    const int t = threadIdx.x;

    if (bid < 1024) {
        // ---- K -> fp16 (single plane) ----
        size_t i = (size_t)bid * 256 + t;   // unit of 8 floats
        float4 a = ((const float4*)K)[i * 2];
        float4 b = ((const float4*)K)[i * 2 + 1];
        uint4 o;
        o.x = pack2h(a.x, a.y);
        o.y = pack2h(a.z, a.w);
        o.z = pack2h(b.x, b.y);
        o.w = pack2h(b.z, b.w);
        ((uint4*)g_Kf)[i] = o;
    } else if (bid < 1536) {
        // ---- V -> B-fragment layout (fp16) ----
        const int v = bid - 1024;
        const int b = v >> 5, c = v & 31;
        const int k0 = c * 64;
        const float* Vb = V + ((size_t)b * N_ + k0) * D_;
#pragma unroll
        for (int it = 0; it < 4; it++) {
            int f = t + it * 256;
            int k = f >> 4, d4 = f & 15;
            float4 vv = *(const float4*)(Vb + k * D_ + d4 * 4);
            smv[k][d4 * 4 + 0] = vv.x;
            smv[k][d4 * 4 + 1] = vv.y;
            smv[k][d4 * 4 + 2] = vv.z;
            smv[k][d4 * 4 + 3] = vv.w;
        }
        __syncthreads();
        const int lane = t & 31;
        const int wslot = t >> 5;   // 0..7, 2 slots each
#pragma unroll
        for (int r = 0; r < 2; r++) {
            int s = wslot * 2 + r;                      // 0..15
            int kh = s >> 3, kg = (s >> 2) & 1, g16 = s & 3;
            int d0 = g16 * 16, kl0 = kh * 32 + kg * 16;
            uint32_t h[4];
#pragma unroll
            for (int i = 0; i < 4; i++) {
                int d = d0 + (i & 1) * 8 + (lane >> 2);
                int kk = kl0 + (i >> 1) * 8 + (lane & 3) * 2;
                h[i] = pack2h(smv[kk][d], smv[kk + 1][d]);
            }
            size_t slot = ((size_t)(b * 32 + c) * 16 + s) * 32 + lane;
            g_VFf[slot] = make_uint4(h[0], h[1], h[2], h[3]);
        }
    } else {
        // ---- Q -> fp16 single plane (scale folded) ----
        size_t i = (size_t)(bid - 1536) * 256 + t;
        float4 a = ((const float4*)Q)[i * 2];
        float4 b = ((const float4*)Q)[i * 2 + 1];
        const float s = 0.125f;
        uint4 o;
        o.x = pack2h(a.x * s, a.y * s);
        o.y = pack2h(a.z * s, a.w * s);
        o.z = pack2h(b.x * s, b.y * s);
        o.w = pack2h(b.z * s, b.w * s);
        ((uint4*)g_Qf)[i] = o;
    }
}

// ---------------------------------------------------------------------------
// Single-pass MMA phase for k1: D = Qf * Kf (both single fp16).
// Buffer: Q@+0 (16K), K@+16384 (8K) => 24KB per buffer
// ---------------------------------------------------------------------------
__device__ __forceinline__ void mma_phase(uint32_t buf, float Dc[2][4][4],
                                          int arow, int brow, int acol) {
#pragma unroll
    for (int ks = 0; ks < 4; ks++) {
        uint32_t aF[2][4], bF[2][4];
#pragma unroll
        for (int mt = 0; mt < 2; mt++)
            ldmx4(aF[mt], buf + SW128((uint32_t)((arow + mt * 16) * 128 + ks * 32 + acol)));
#pragma unroll
        for (int np = 0; np < 2; np++)
            ldmx4(bF[np], buf + 16384 + SW128((uint32_t)((brow + np * 16) * 128 + ks * 32 + acol)));
#pragma unroll
        for (int mt = 0; mt < 2; mt++)
#pragma unroll
            for (int np = 0; np < 2; np++) {
                mma16816(Dc[mt][np * 2],     aF[mt], bF[np][0], bF[np][2]);
                mma16816(Dc[mt][np * 2 + 1], aF[mt], bF[np][1], bF[np][3]);
            }
    }
}

// ===========================================================================
// k1: scores. Double-buffered cp.async staging of Q+K (single fp16 planes);
// P stored fp16 fragment-tiled (coalesced STG.64), rdenom fp32.
// ===========================================================================
__device__ __forceinline__ void k1_stage(uint32_t buf, int tid, size_t qbase, size_t kbase) {
#pragma unroll
    for (int it = 0; it < 4; it++) {
        int u = tid + it * 256;
        int q = u >> 3, g = u & 7;
        cp16(buf + SW128((uint32_t)(q * 128 + g * 16)),
             g_Qf + qbase + q * D_ + g * 8);
    }
#pragma unroll
    for (int it = 0; it < 2; it++) {
        int u = tid + it * 256;
        int k = u >> 3, g = u & 7;
        cp16(buf + 16384 + SW128((uint32_t)(k * 128 + g * 16)),
             g_Kf + kbase + k * D_ + g * 8);
    }
    cp_commit();
}

__global__ __launch_bounds__(256, 2) void k1_scores() {
    extern __shared__ __align__(128) uint8_t smem[];   // 49152
    const uint32_t sb = smem_u32(smem);
    const int tid = threadIdx.x;
    const int lane = tid & 31, w = tid >> 5;
    const int kt = blockIdx.x, qt = blockIdx.y;
    const int q0 = qt * 128, k0 = kt * 64;
    const int wq = w >> 1, wk = w & 1;
    const int arow = wq * 32 + (lane & 15);
    const int brow = wk * 32 + (lane & 15);
    const int acol = (lane >> 4) * 16;
    const int fragoff = w * 1024 + lane * 4;

    float denom[2][4][4];
#pragma unroll
    for (int mt = 0; mt < 2; mt++)
#pragma unroll
        for (int nt = 0; nt < 4; nt++)
#pragma unroll
            for (int r = 0; r < 4; r++) denom[mt][nt][r] = 0.0f;

    k1_stage(sb,         tid, (size_t)0 * ND + (size_t)q0 * D_, (size_t)0 * ND + (size_t)k0 * D_);
    k1_stage(sb + 24576, tid, (size_t)1 * ND + (size_t)q0 * D_, (size_t)1 * ND + (size_t)k0 * D_);

    for (int b = 0; b < B_; b++) {
        const uint32_t buf = sb + (b & 1) * 24576;
        if (b < B_ - 1) asm volatile("cp.async.wait_group 1;" ::: "memory");
        else            asm volatile("cp.async.wait_group 0;" ::: "memory");
        __syncthreads();

        float Dc[2][4][4];
#pragma unroll
        for (int mt = 0; mt < 2; mt++)
#pragma unroll
            for (int nt = 0; nt < 4; nt++)
#pragma unroll
                for (int r = 0; r < 4; r++) Dc[mt][nt][r] = 0.0f;

        mma_phase(buf, Dc, arow, brow, acol);

        // ---- exp + denom + fragment-tiled coalesced fp16 P store ----
        __half* Pb = g_P + (((size_t)b * 16 + qt) * 32 + kt) * TILE + fragoff;
#pragma unroll
        for (int mt = 0; mt < 2; mt++)
#pragma unroll
            for (int nt = 0; nt < 4; nt++) {
                float e0 = __expf(Dc[mt][nt][0]);
                float e1 = __expf(Dc[mt][nt][1]);
                float e2 = __expf(Dc[mt][nt][2]);
                float e3 = __expf(Dc[mt][nt][3]);
                denom[mt][nt][0] += e0; denom[mt][nt][1] += e1;
                denom[mt][nt][2] += e2; denom[mt][nt][3] += e3;
                *(uint2*)(Pb + (mt * 4 + nt) * 128) =
                    make_uint2(pack2h(e0, e1), pack2h(e2, e3));
            }
        __syncthreads();
        if (b + 2 < B_)
            k1_stage(buf, tid, (size_t)(b + 2) * ND + (size_t)q0 * D_,
                               (size_t)(b + 2) * ND + (size_t)k0 * D_);
    }

    // ---- rdenom (fragment-tiled, coalesced, fp32) ----
    float* Rb = g_rdenom + ((size_t)qt * 32 + kt) * TILE + fragoff;
#pragma unroll
    for (int mt = 0; mt < 2; mt++)
#pragma unroll
        for (int nt = 0; nt < 4; nt++)
            *(float4*)(Rb + (mt * 4 + nt) * 128) = make_float4(
                1.0f / denom[mt][nt][0], 1.0f / denom[mt][nt][1],
                1.0f / denom[mt][nt][2], 1.0f / denom[mt][nt][3]);
}

// ===========================================================================
// k2: out[b] = (P[b]*rdenom) @ V[b]. Block (b, qt), 256 thr.
// P prefetched per-thread via 8-byte cp.async into private smem slots
// (depth-1 double buffer, same-thread commit/wait => NO barriers in loop).
// A = fp16(P)*rdenom; V single fp16 via LDG (L2). Epilogue reduction reuses
// the smem P region after the loop.
// smem: pbuf[2] @0..32KB, red @32KB..64KB => 65536 dynamic
// ===========================================================================
__global__ __launch_bounds__(256, 2) void k2_out(float* __restrict__ O) {
    extern __shared__ __align__(128) uint8_t smem[];   // 65536
    const uint32_t sb = smem_u32(smem);
    float* red = (float*)(smem + 32768);
    const int tid = threadIdx.x;
    const int lane = tid & 31, w = tid >> 5;
    const int b = blockIdx.x, qt = blockIdx.y;
    const int wq2 = w >> 1, kh = w & 1;
    const int fragoff = w * 1024 + lane * 4;          // halves, in P tile
    // per-thread smem slot: fragment i at pslot + i*256 bytes
    const uint32_t pslot = sb + (uint32_t)(w * 2048 + lane * 8);

    float Dc[2][8][4];
#pragma unroll
    for (int mt = 0; mt < 2; mt++)
#pragma unroll
        for (int j = 0; j < 8; j++)
#pragma unroll
            for (int r = 0; r < 4; r++) Dc[mt][j][r] = 0.0f;

    const size_t tb = ((size_t)b * 16 + qt) * 32;     // tile index base

    // ---- stage chunk 0 ----
    {
        const __half* pA = g_P + tb * TILE + fragoff;
#pragma unroll
        for (int i = 0; i < 8; i++)
            cp8(pslot + i * 256, pA + i * 128);
        cp_commit();
    }

    for (int c = 0; c < 32; c++) {
        const uint32_t buf = pslot + (uint32_t)((c & 1) * 16384);
        if (c + 1 < 32) {
            const __half* pA = g_P + (tb + c + 1) * TILE + fragoff;
            const uint32_t nbuf = pslot + (uint32_t)(((c + 1) & 1) * 16384);
#pragma unroll
            for (int i = 0; i < 8; i++)
                cp8(nbuf + i * 256, pA + i * 128);
            cp_commit();
            asm volatile("cp.async.wait_group 1;" ::: "memory");
        } else {
            asm volatile("cp.async.wait_group 0;" ::: "memory");
        }

        const float* pR = g_rdenom + ((size_t)qt * 32 + c) * TILE + fragoff;
        const size_t vbase = ((size_t)(b * 32 + c) * 16 + kh * 8) * 32 + lane;

#pragma unroll
        for (int kg = 0; kg < 2; kg++) {
            uint32_t aH[2][4];
#pragma unroll
            for (int mt = 0; mt < 2; mt++)
#pragma unroll
                for (int hf = 0; hf < 2; hf++) {
                    int i = mt * 4 + kg * 2 + hf;
                    uint32_t p0, p1;
                    asm volatile("ld.shared.v2.u32 {%0,%1}, [%2];"
                                 : "=r"(p0), "=r"(p1) : "r"(buf + i * 256));
                    float4 r = *(const float4*)(pR + i * 128);
                    float2 p01 = __half22float2(*(__half2*)&p0);
                    float2 p23 = __half22float2(*(__half2*)&p1);
                    aH[mt][hf * 2]     = pack2h(p01.x * r.x, p01.y * r.y);
                    aH[mt][hf * 2 + 1] = pack2h(p23.x * r.z, p23.y * r.w);
                }
#pragma unroll
            for (int g16 = 0; g16 < 4; g16++) {
                uint4 vh = g_VFf[vbase + (size_t)(kg * 4 + g16) * 32];
#pragma unroll
                for (int mt = 0; mt < 2; mt++) {
                    mma16816(Dc[mt][g16 * 2],     aH[mt], vh.x, vh.z);
                    mma16816(Dc[mt][g16 * 2 + 1], aH[mt], vh.y, vh.w);
                }
            }
        }
    }

    // ---- cross-warp (kh) reduction via smem, then O store ----
    __syncthreads();   // everyone done with pbuf region (red is separate)
    if (kh == 1) {
#pragma unroll
        for (int mt = 0; mt < 2; mt++)
#pragma unroll
            for (int j = 0; j < 8; j++)
                *(float4*)(red + wq2 * 2048 + (mt * 8 + j) * 128 + lane * 4) =
                    make_float4(Dc[mt][j][0], Dc[mt][j][1], Dc[mt][j][2], Dc[mt][j][3]);
    }
    __syncthreads();
    if (kh == 0) {
#pragma unroll
        for (int mt = 0; mt < 2; mt++) {
            int r0 = qt * 128 + wq2 * 32 + mt * 16 + (lane >> 2);
#pragma unroll
            for (int j = 0; j < 8; j++) {
                float4 o = *(float4*)(red + wq2 * 2048 + (mt * 8 + j) * 128 + lane * 4);
                float v0 = Dc[mt][j][0] + o.x;
                float v1 = Dc[mt][j][1] + o.y;
                float v2 = Dc[mt][j][2] + o.z;
                float v3 = Dc[mt][j][3] + o.w;
                int cc = j * 8 + 2 * (lane & 3);
                *(float2*)(O + ((size_t)b * N_ + r0) * D_ + cc)     = make_float2(v0, v1);
                *(float2*)(O + ((size_t)b * N_ + r0 + 8) * D_ + cc) = make_float2(v2, v3);
            }
        }
    }
}

// ===========================================================================
extern "C" void kernel_launch(void* const* d_in, const int* in_sizes, int n_in,
                              void* d_out, int out_size) {
    const float* Q = (const float*)d_in[0];
    const float* K = (const float*)d_in[1];
    const float* V = (const float*)d_in[2];
    float* O = (float*)d_out;

    cudaFuncSetAttribute(k1_scores, cudaFuncAttributeMaxDynamicSharedMemorySize, 49152);
    cudaFuncSetAttribute(k2_out, cudaFuncAttributeMaxDynamicSharedMemorySize, 65536);

    k0_prep<<<2560, 256>>>(Q, K, V);
    k1_scores<<<dim3(N_ / 64, N_ / 128), 256, 49152>>>();   // (kt, qt)
    k2_out<<<dim3(B_, N_ / 128), 256, 65536>>>(O);          // (b, qt)
}